// round 2
// baseline (speedup 1.0000x reference)
#include <cuda_runtime.h>

#define NN 100000
#define NE 3200000
#define HID 16

typedef unsigned long long u64;

// ---------------- scratch ----------------
__device__ float g_e[NE][HID];        // 204.8 MB edge features
__device__ float g_agg_s[NN][HID];    // 6.4 MB
__device__ float g_agg_r[NN][HID];    // 6.4 MB
__device__ float g_nodes[NN];
__device__ float g_part[1024];        // block maxima for norm
__device__ float g_norm;

// ---------------- f32x2 packed helpers ----------------
__device__ __forceinline__ u64 pk2(float lo, float hi) {
    u64 r;
    asm("mov.b64 %0, {%1, %2};" : "=l"(r)
        : "r"(__float_as_uint(lo)), "r"(__float_as_uint(hi)));
    return r;
}
__device__ __forceinline__ void up2(u64 v, float& x, float& y) {
    unsigned a, b;
    asm("mov.b64 {%0, %1}, %2;" : "=r"(a), "=r"(b) : "l"(v));
    x = __uint_as_float(a); y = __uint_as_float(b);
}
__device__ __forceinline__ u64 fma2(u64 a, u64 b, u64 c) {
    u64 d;
    asm("fma.rn.f32x2 %0, %1, %2, %3;" : "=l"(d) : "l"(a), "l"(b), "l"(c));
    return d;
}
__device__ __forceinline__ u64 relu2(u64 v) {
    float x, y; up2(v, x, y);
    return pk2(fmaxf(x, 0.f), fmaxf(y, 0.f));
}

__device__ __forceinline__ void red_add_v4(float* p, float a, float b, float c, float d) {
    asm volatile("red.global.add.v4.f32 [%0], {%1, %2, %3, %4};"
                 :: "l"(p), "f"(a), "f"(b), "f"(c), "f"(d) : "memory");
}

// ---------------- launch 0: zero agg buffers ----------------
__global__ void k_zero() {
    int i = blockIdx.x * blockDim.x + threadIdx.x;
    const int nf4 = NN * HID / 4;
    float4 z = make_float4(0.f, 0.f, 0.f, 0.f);
    if (i < nf4) {
        ((float4*)g_agg_s)[i] = z;
        ((float4*)g_agg_r)[i] = z;
    }
}

// ---------------- launch 1: per-block max |x| ----------------
__global__ __launch_bounds__(256) void k_norm_part(const float* __restrict__ x) {
    __shared__ float sm[8];
    float m = 0.f;
    const float4* x4 = (const float4*)x;
    const int n4 = NE / 4;
    for (int i = blockIdx.x * blockDim.x + threadIdx.x; i < n4; i += gridDim.x * blockDim.x) {
        float4 v = x4[i];
        m = fmaxf(m, fmaxf(fmaxf(fabsf(v.x), fabsf(v.y)), fmaxf(fabsf(v.z), fabsf(v.w))));
    }
#pragma unroll
    for (int o = 16; o; o >>= 1) m = fmaxf(m, __shfl_xor_sync(0xffffffffu, m, o));
    if ((threadIdx.x & 31) == 0) sm[threadIdx.x >> 5] = m;
    __syncthreads();
    if (threadIdx.x < 8) {
        m = sm[threadIdx.x];
#pragma unroll
        for (int o = 4; o; o >>= 1) m = fmaxf(m, __shfl_xor_sync(0xffu, m, o));
        if (threadIdx.x == 0) g_part[blockIdx.x] = m;
    }
}

// ---------------- launch 2: finalize norm (1 block) ----------------
__global__ __launch_bounds__(1024) void k_norm_final() {
    __shared__ float sm[32];
    float m = g_part[threadIdx.x];
#pragma unroll
    for (int o = 16; o; o >>= 1) m = fmaxf(m, __shfl_xor_sync(0xffffffffu, m, o));
    if ((threadIdx.x & 31) == 0) sm[threadIdx.x >> 5] = m;
    __syncthreads();
    if (threadIdx.x < 32) {
        m = sm[threadIdx.x];
#pragma unroll
        for (int o = 16; o; o >>= 1) m = fmaxf(m, __shfl_xor_sync(0xffffffffu, m, o));
        if (threadIdx.x == 0) g_norm = m;
    }
}

// ---------------- launch 3: encoder (2 edges/thread, packed) ----------------
__global__ __launch_bounds__(256) void k_enc(
    const float* __restrict__ edges_init,
    const int* __restrict__ senders, const int* __restrict__ receivers,
    const float* __restrict__ w1g, const float* __restrict__ b1g,
    const float* __restrict__ w2g, const float* __restrict__ b2g)
{
    __shared__ u64 w1[HID], b1[HID], w2[HID * HID], b2[HID];
    int t = threadIdx.x;
    if (t < HID) {
        w1[t] = pk2(w1g[t], w1g[t]);
        b1[t] = pk2(b1g[t], b1g[t]);
        b2[t] = pk2(b2g[t], b2g[t]);
    }
    for (int i = t; i < HID * HID; i += blockDim.x) w2[i] = pk2(w2g[i], w2g[i]);
    __syncthreads();

    int p = blockIdx.x * blockDim.x + t;
    if (p >= NE / 2) return;
    int i0 = 2 * p;

    float inv = g_norm;
    float2 xi = ((const float2*)edges_init)[p];
    u64 X = pk2(xi.x / inv, xi.y / inv);

    u64 h[HID];
#pragma unroll
    for (int j = 0; j < HID; j++) h[j] = relu2(fma2(w1[j], X, b1[j]));

    u64 e[HID];
#pragma unroll
    for (int j = 0; j < HID; j++) {
        u64 a = b2[j];
#pragma unroll
        for (int k = 0; k < HID; k++) a = fma2(w2[j * HID + k], h[k], a);
        e[j] = a;
    }

    float ea[HID], eb[HID];
#pragma unroll
    for (int j = 0; j < HID; j++) up2(e[j], ea[j], eb[j]);

    float4* ep0 = (float4*)g_e[i0];
    float4* ep1 = (float4*)g_e[i0 + 1];
#pragma unroll
    for (int q = 0; q < 4; q++) {
        ep0[q] = make_float4(ea[4 * q], ea[4 * q + 1], ea[4 * q + 2], ea[4 * q + 3]);
        ep1[q] = make_float4(eb[4 * q], eb[4 * q + 1], eb[4 * q + 2], eb[4 * q + 3]);
    }

    int2 s2 = ((const int2*)senders)[p];
    int2 r2 = ((const int2*)receivers)[p];
#pragma unroll
    for (int q = 0; q < 4; q++) {
        red_add_v4(g_agg_s[s2.x] + 4 * q, ea[4 * q], ea[4 * q + 1], ea[4 * q + 2], ea[4 * q + 3]);
        red_add_v4(g_agg_r[r2.x] + 4 * q, ea[4 * q], ea[4 * q + 1], ea[4 * q + 2], ea[4 * q + 3]);
        red_add_v4(g_agg_s[s2.y] + 4 * q, eb[4 * q], eb[4 * q + 1], eb[4 * q + 2], eb[4 * q + 3]);
        red_add_v4(g_agg_r[r2.y] + 4 * q, eb[4 * q], eb[4 * q + 1], eb[4 * q + 2], eb[4 * q + 3]);
    }
}

// ---------------- node update (2 nodes/thread, packed) ----------------
template <bool FIRST>
__global__ __launch_bounds__(256) void k_node(
    const float* __restrict__ in_nodes,
    const float* __restrict__ w1g, const float* __restrict__ b1g,
    const float* __restrict__ w2g, const float* __restrict__ b2g)
{
    __shared__ u64 w1[HID * 33], b1[HID], w2[HID];
    __shared__ float b2s;
    int t = threadIdx.x;
    for (int i = t; i < HID * 33; i += blockDim.x) w1[i] = pk2(w1g[i], w1g[i]);
    if (t < HID) { b1[t] = pk2(b1g[t], b1g[t]); w2[t] = pk2(w2g[t], w2g[t]); }
    if (t == 0) b2s = b2g[0];
    __syncthreads();

    int p = blockIdx.x * blockDim.x + t;
    if (p >= NN / 2) return;
    int n0 = 2 * p;

    u64 xin[33];
    if (FIRST) {
        float2 nd = ((const float2*)in_nodes)[p];
        xin[0] = pk2(nd.x, nd.y);
    } else {
        float2 nd = ((const float2*)g_nodes)[p];
        xin[0] = pk2(nd.x, nd.y);
    }
    float4* as0 = (float4*)g_agg_s[n0];
    float4* as1 = (float4*)g_agg_s[n0 + 1];
    float4* ar0 = (float4*)g_agg_r[n0];
    float4* ar1 = (float4*)g_agg_r[n0 + 1];
#pragma unroll
    for (int q = 0; q < 4; q++) {
        float4 a = as0[q], b = as1[q];
        xin[1 + 4 * q] = pk2(a.x, b.x); xin[2 + 4 * q] = pk2(a.y, b.y);
        xin[3 + 4 * q] = pk2(a.z, b.z); xin[4 + 4 * q] = pk2(a.w, b.w);
        float4 c = ar0[q], d = ar1[q];
        xin[17 + 4 * q] = pk2(c.x, d.x); xin[18 + 4 * q] = pk2(c.y, d.y);
        xin[19 + 4 * q] = pk2(c.z, d.z); xin[20 + 4 * q] = pk2(c.w, d.w);
    }
    // re-zero aggs for next scatter round
    float4 z = make_float4(0.f, 0.f, 0.f, 0.f);
#pragma unroll
    for (int q = 0; q < 4; q++) { as0[q] = z; as1[q] = z; ar0[q] = z; ar1[q] = z; }

    u64 out = pk2(b2s, b2s);
#pragma unroll
    for (int j = 0; j < HID; j++) {
        u64 hj = b1[j];
#pragma unroll
        for (int c = 0; c < 33; c++) hj = fma2(w1[j * 33 + c], xin[c], hj);
        out = fma2(w2[j], relu2(hj), out);
    }
    float oa, ob; up2(out, oa, ob);
    ((float2*)g_nodes)[p] = make_float2(oa, ob);
}

// ---------------- edge update (2 edges/thread, packed) ----------------
template <bool LAST>
__global__ __launch_bounds__(256) void k_edge(
    const int* __restrict__ senders, const int* __restrict__ receivers,
    const float* __restrict__ ew1g, const float* __restrict__ eb1g,
    const float* __restrict__ ew2g, const float* __restrict__ eb2g,
    const float* __restrict__ dw1g, const float* __restrict__ db1g,
    const float* __restrict__ dw2g, const float* __restrict__ db2g,
    const float* __restrict__ edges_init, const float* __restrict__ alpha_p,
    float* __restrict__ out)
{
    __shared__ u64 ew1[HID * 18], eb1[HID], ew2[HID * HID], eb2[HID];
    __shared__ u64 dw1[HID * HID], db1[HID], dw2[HID];
    __shared__ float db2s, alphas;
    int t = threadIdx.x;
    for (int i = t; i < HID * 18; i += blockDim.x) ew1[i] = pk2(ew1g[i], ew1g[i]);
    for (int i = t; i < HID * HID; i += blockDim.x) ew2[i] = pk2(ew2g[i], ew2g[i]);
    if (t < HID) { eb1[t] = pk2(eb1g[t], eb1g[t]); eb2[t] = pk2(eb2g[t], eb2g[t]); }
    if (LAST) {
        for (int i = t; i < HID * HID; i += blockDim.x) dw1[i] = pk2(dw1g[i], dw1g[i]);
        if (t < HID) { db1[t] = pk2(db1g[t], db1g[t]); dw2[t] = pk2(dw2g[t], dw2g[t]); }
        if (t == 0) { db2s = db2g[0]; alphas = alpha_p[0]; }
    }
    __syncthreads();

    int p = blockIdx.x * blockDim.x + t;
    if (p >= NE / 2) return;
    int i0 = 2 * p;

    u64 e[HID];
    float4* ep0 = (float4*)g_e[i0];
    float4* ep1 = (float4*)g_e[i0 + 1];
#pragma unroll
    for (int q = 0; q < 4; q++) {
        float4 a = ep0[q], b = ep1[q];
        e[4 * q]     = pk2(a.x, b.x);
        e[4 * q + 1] = pk2(a.y, b.y);
        e[4 * q + 2] = pk2(a.z, b.z);
        e[4 * q + 3] = pk2(a.w, b.w);
    }
    int2 s2 = ((const int2*)senders)[p];
    int2 r2 = ((const int2*)receivers)[p];
    u64 NS = pk2(g_nodes[s2.x], g_nodes[s2.y]);
    u64 NR = pk2(g_nodes[r2.x], g_nodes[r2.y]);

    u64 h[HID];
#pragma unroll
    for (int j = 0; j < HID; j++) {
        u64 a = eb1[j];
#pragma unroll
        for (int k = 0; k < HID; k++) a = fma2(ew1[j * 18 + k], e[k], a);
        a = fma2(ew1[j * 18 + 16], NS, a);
        a = fma2(ew1[j * 18 + 17], NR, a);
        h[j] = relu2(a);
    }
    u64 e2[HID];
#pragma unroll
    for (int j = 0; j < HID; j++) {
        u64 a = eb2[j];
#pragma unroll
        for (int k = 0; k < HID; k++) a = fma2(ew2[j * HID + k], h[k], a);
        e2[j] = a;
    }

    if (!LAST) {
        float ea[HID], eb[HID];
#pragma unroll
        for (int j = 0; j < HID; j++) up2(e2[j], ea[j], eb[j]);
#pragma unroll
        for (int q = 0; q < 4; q++) {
            ep0[q] = make_float4(ea[4 * q], ea[4 * q + 1], ea[4 * q + 2], ea[4 * q + 3]);
            ep1[q] = make_float4(eb[4 * q], eb[4 * q + 1], eb[4 * q + 2], eb[4 * q + 3]);
        }
#pragma unroll
        for (int q = 0; q < 4; q++) {
            red_add_v4(g_agg_s[s2.x] + 4 * q, ea[4 * q], ea[4 * q + 1], ea[4 * q + 2], ea[4 * q + 3]);
            red_add_v4(g_agg_r[r2.x] + 4 * q, ea[4 * q], ea[4 * q + 1], ea[4 * q + 2], ea[4 * q + 3]);
            red_add_v4(g_agg_s[s2.y] + 4 * q, eb[4 * q], eb[4 * q + 1], eb[4 * q + 2], eb[4 * q + 3]);
            red_add_v4(g_agg_r[r2.y] + 4 * q, eb[4 * q], eb[4 * q + 1], eb[4 * q + 2], eb[4 * q + 3]);
        }
    } else {
        u64 h2[HID];
#pragma unroll
        for (int j = 0; j < HID; j++) {
            u64 a = db1[j];
#pragma unroll
            for (int k = 0; k < HID; k++) a = fma2(dw1[j * HID + k], e2[k], a);
            h2[j] = relu2(a);
        }
        u64 sdec = pk2(db2s, db2s);
#pragma unroll
        for (int k = 0; k < HID; k++) sdec = fma2(dw2[k], h2[k], sdec);
        float sa, sb; up2(sdec, sa, sb);
        float scale = alphas * g_norm;
        float2 ei = ((const float2*)edges_init)[p];
        ((float2*)out)[p] = make_float2(fmaf(scale, sa, ei.x), fmaf(scale, sb, ei.y));
    }
}

// ---------------- launch ----------------
extern "C" void kernel_launch(void* const* d_in, const int* in_sizes, int n_in,
                              void* d_out, int out_size)
{
    const float* nodes      = (const float*)d_in[0];
    const float* edges_init = (const float*)d_in[1];
    const int*   senders    = (const int*)d_in[2];
    const int*   receivers  = (const int*)d_in[3];
    const float* enc_w1 = (const float*)d_in[4];
    const float* enc_b1 = (const float*)d_in[5];
    const float* enc_w2 = (const float*)d_in[6];
    const float* enc_b2 = (const float*)d_in[7];
    const float* node_w1 = (const float*)d_in[8];
    const float* node_b1 = (const float*)d_in[9];
    const float* node_w2 = (const float*)d_in[10];
    const float* node_b2 = (const float*)d_in[11];
    const float* edge_w1 = (const float*)d_in[12];
    const float* edge_b1 = (const float*)d_in[13];
    const float* edge_w2 = (const float*)d_in[14];
    const float* edge_b2 = (const float*)d_in[15];
    const float* dec_w1 = (const float*)d_in[16];
    const float* dec_b1 = (const float*)d_in[17];
    const float* dec_w2 = (const float*)d_in[18];
    const float* dec_b2 = (const float*)d_in[19];
    const float* alpha  = (const float*)d_in[20];
    float* out = (float*)d_out;

    const int TB = 256;
    int zb = (NN * HID / 4 + TB - 1) / TB;
    k_zero<<<zb, TB>>>();                       // launch 0
    k_norm_part<<<1024, TB>>>(edges_init);      // launch 1
    k_norm_final<<<1, 1024>>>();                // launch 2

    int eb = (NE / 2 + TB - 1) / TB;
    int nb = (NN / 2 + TB - 1) / TB;

    k_enc<<<eb, TB>>>(edges_init, senders, receivers,
                      enc_w1, enc_b1, enc_w2, enc_b2);   // launch 3

    for (int r = 0; r < 3; r++) {
        if (r == 0)
            k_node<true><<<nb, TB>>>(nodes, node_w1, node_b1, node_w2, node_b2);
        else
            k_node<false><<<nb, TB>>>(nodes, node_w1, node_b1, node_w2, node_b2);

        if (r < 2)
            k_edge<false><<<eb, TB>>>(senders, receivers,
                                      edge_w1, edge_b1, edge_w2, edge_b2,
                                      dec_w1, dec_b1, dec_w2, dec_b2,
                                      edges_init, alpha, out);
        else
            k_edge<true><<<eb, TB>>>(senders, receivers,
                                     edge_w1, edge_b1, edge_w2, edge_b2,
                                     dec_w1, dec_b1, dec_w2, dec_b2,
                                     edges_init, alpha, out);
    }
}

// round 3
// speedup vs baseline: 1.7280x; 1.7280x over previous
#include <cuda_runtime.h>
#include <cuda_fp16.h>

#define NN 100000
#define NE 3200000
#define HID 16

typedef unsigned int u32;

// ---------------- scratch ----------------
__device__ __half g_e[NE][HID];       // 102.4 MB edge features (f16)
__device__ __half g_agg_s[NN][HID];   // 3.2 MB (f16 accumulators)
__device__ __half g_agg_r[NN][HID];   // 3.2 MB
__device__ float  g_nodes[NN];
__device__ float  g_part[1024];
__device__ float  g_norm;

// ---------------- helpers ----------------
__device__ __forceinline__ u32 packh2(float a, float b) {
    __half2 h = __floats2half2_rn(a, b);
    return *(u32*)&h;
}
__device__ __forceinline__ float2 unpackh2(u32 v) {
    __half2 h = *(__half2*)&v;
    return __half22float2(h);
}
// vector f16x2 reduction: 16 bytes = 8 halves per op
__device__ __forceinline__ void red_add_v4h(void* p, u32 a, u32 b, u32 c, u32 d) {
    asm volatile("red.global.add.noftz.v4.f16x2 [%0], {%1, %2, %3, %4};"
                 :: "l"(p), "r"(a), "r"(b), "r"(c), "r"(d) : "memory");
}

// ---------------- launch 0: zero agg buffers ----------------
__global__ void k_zero() {
    int i = blockIdx.x * blockDim.x + threadIdx.x;
    const int nf4 = NN * HID * 2 / 16;   // 16B chunks per buffer
    uint4 z = make_uint4(0u, 0u, 0u, 0u);
    if (i < nf4) {
        ((uint4*)g_agg_s)[i] = z;
        ((uint4*)g_agg_r)[i] = z;
    }
}

// ---------------- launch 1: per-block max |x| ----------------
__global__ __launch_bounds__(256) void k_norm_part(const float* __restrict__ x) {
    __shared__ float sm[8];
    float m = 0.f;
    const float4* x4 = (const float4*)x;
    const int n4 = NE / 4;
    for (int i = blockIdx.x * blockDim.x + threadIdx.x; i < n4; i += gridDim.x * blockDim.x) {
        float4 v = x4[i];
        m = fmaxf(m, fmaxf(fmaxf(fabsf(v.x), fabsf(v.y)), fmaxf(fabsf(v.z), fabsf(v.w))));
    }
#pragma unroll
    for (int o = 16; o; o >>= 1) m = fmaxf(m, __shfl_xor_sync(0xffffffffu, m, o));
    if ((threadIdx.x & 31) == 0) sm[threadIdx.x >> 5] = m;
    __syncthreads();
    if (threadIdx.x < 8) {
        m = sm[threadIdx.x];
#pragma unroll
        for (int o = 4; o; o >>= 1) m = fmaxf(m, __shfl_xor_sync(0xffu, m, o));
        if (threadIdx.x == 0) g_part[blockIdx.x] = m;
    }
}

// ---------------- launch 2: finalize norm ----------------
__global__ __launch_bounds__(1024) void k_norm_final() {
    __shared__ float sm[32];
    float m = g_part[threadIdx.x];
#pragma unroll
    for (int o = 16; o; o >>= 1) m = fmaxf(m, __shfl_xor_sync(0xffffffffu, m, o));
    if ((threadIdx.x & 31) == 0) sm[threadIdx.x >> 5] = m;
    __syncthreads();
    if (threadIdx.x < 32) {
        m = sm[threadIdx.x];
#pragma unroll
        for (int o = 16; o; o >>= 1) m = fmaxf(m, __shfl_xor_sync(0xffffffffu, m, o));
        if (threadIdx.x == 0) g_norm = m;
    }
}

// ---------------- launch 3: encoder ----------------
__global__ __launch_bounds__(256) void k_enc(
    const float* __restrict__ edges_init,
    const int* __restrict__ senders, const int* __restrict__ receivers,
    const float* __restrict__ w1g, const float* __restrict__ b1g,
    const float* __restrict__ w2g, const float* __restrict__ b2g)
{
    __shared__ float w1[HID], b1[HID], w2[HID * HID], b2[HID];
    int t = threadIdx.x;
    if (t < HID) { w1[t] = w1g[t]; b1[t] = b1g[t]; b2[t] = b2g[t]; }
    for (int i = t; i < HID * HID; i += blockDim.x) w2[i] = w2g[i];
    __syncthreads();

    int i = blockIdx.x * blockDim.x + t;
    if (i >= NE) return;

    float x = edges_init[i] / g_norm;
    float h[HID];
#pragma unroll
    for (int j = 0; j < HID; j++) h[j] = fmaxf(fmaf(w1[j], x, b1[j]), 0.f);
    float e[HID];
#pragma unroll
    for (int j = 0; j < HID; j++) {
        float a = b2[j];
#pragma unroll
        for (int k = 0; k < HID; k++) a = fmaf(w2[j * HID + k], h[k], a);
        e[j] = a;
    }

    u32 u[8];
#pragma unroll
    for (int q = 0; q < 8; q++) u[q] = packh2(e[2 * q], e[2 * q + 1]);

    uint4* ep = (uint4*)g_e[i];
    ep[0] = make_uint4(u[0], u[1], u[2], u[3]);
    ep[1] = make_uint4(u[4], u[5], u[6], u[7]);

    int s = senders[i], r = receivers[i];
    char* ps = (char*)g_agg_s + (size_t)s * 32;
    char* pr = (char*)g_agg_r + (size_t)r * 32;
    red_add_v4h(ps,      u[0], u[1], u[2], u[3]);
    red_add_v4h(ps + 16, u[4], u[5], u[6], u[7]);
    red_add_v4h(pr,      u[0], u[1], u[2], u[3]);
    red_add_v4h(pr + 16, u[4], u[5], u[6], u[7]);
}

// ---------------- node update: read + re-zero aggs, MLP 33->16->1 ----------------
template <bool FIRST>
__global__ __launch_bounds__(256) void k_node(
    const float* __restrict__ in_nodes,
    const float* __restrict__ w1g, const float* __restrict__ b1g,
    const float* __restrict__ w2g, const float* __restrict__ b2g)
{
    __shared__ float w1[HID * 33], b1[HID], w2[HID], b2s;
    int t = threadIdx.x;
    for (int i = t; i < HID * 33; i += blockDim.x) w1[i] = w1g[i];
    if (t < HID) { b1[t] = b1g[t]; w2[t] = w2g[t]; }
    if (t == 0) b2s = b2g[0];
    __syncthreads();

    int n = blockIdx.x * blockDim.x + t;
    if (n >= NN) return;

    float xin[33];
    xin[0] = FIRST ? in_nodes[n] : g_nodes[n];
    uint4* as4 = (uint4*)g_agg_s[n];
    uint4* ar4 = (uint4*)g_agg_r[n];
#pragma unroll
    for (int half = 0; half < 2; half++) {
        uint4 a = as4[half];
        u32 w[4] = {a.x, a.y, a.z, a.w};
#pragma unroll
        for (int q = 0; q < 4; q++) {
            float2 f = unpackh2(w[q]);
            xin[1 + half * 8 + 2 * q] = f.x;
            xin[2 + half * 8 + 2 * q] = f.y;
        }
        uint4 b = ar4[half];
        u32 v[4] = {b.x, b.y, b.z, b.w};
#pragma unroll
        for (int q = 0; q < 4; q++) {
            float2 f = unpackh2(v[q]);
            xin[17 + half * 8 + 2 * q] = f.x;
            xin[18 + half * 8 + 2 * q] = f.y;
        }
    }
    // re-zero aggs for the next scatter round
    uint4 z = make_uint4(0u, 0u, 0u, 0u);
    as4[0] = z; as4[1] = z; ar4[0] = z; ar4[1] = z;

    float out = b2s;
#pragma unroll
    for (int j = 0; j < HID; j++) {
        float hj = b1[j];
#pragma unroll
        for (int c = 0; c < 33; c++) hj = fmaf(w1[j * 33 + c], xin[c], hj);
        out = fmaf(w2[j], fmaxf(hj, 0.f), out);
    }
    g_nodes[n] = out;
}

// ---------------- edge update (+scatter, or fused decoder+residual) ----------------
template <bool LAST>
__global__ __launch_bounds__(256) void k_edge(
    const int* __restrict__ senders, const int* __restrict__ receivers,
    const float* __restrict__ ew1g, const float* __restrict__ eb1g,
    const float* __restrict__ ew2g, const float* __restrict__ eb2g,
    const float* __restrict__ dw1g, const float* __restrict__ db1g,
    const float* __restrict__ dw2g, const float* __restrict__ db2g,
    const float* __restrict__ edges_init, const float* __restrict__ alpha_p,
    float* __restrict__ out)
{
    __shared__ float ew1[HID * 18], eb1[HID], ew2[HID * HID], eb2[HID];
    __shared__ float dw1[HID * HID], db1[HID], dw2[HID], db2s, alphas;
    int t = threadIdx.x;
    for (int i = t; i < HID * 18; i += blockDim.x) ew1[i] = ew1g[i];
    for (int i = t; i < HID * HID; i += blockDim.x) ew2[i] = ew2g[i];
    if (t < HID) { eb1[t] = eb1g[t]; eb2[t] = eb2g[t]; }
    if (LAST) {
        for (int i = t; i < HID * HID; i += blockDim.x) dw1[i] = dw1g[i];
        if (t < HID) { db1[t] = db1g[t]; dw2[t] = dw2g[t]; }
        if (t == 0) { db2s = db2g[0]; alphas = alpha_p[0]; }
    }
    __syncthreads();

    int i = blockIdx.x * blockDim.x + t;
    if (i >= NE) return;

    uint4* ep = (uint4*)g_e[i];
    float e[HID];
    {
        uint4 a = ep[0], b = ep[1];
        u32 w[8] = {a.x, a.y, a.z, a.w, b.x, b.y, b.z, b.w};
#pragma unroll
        for (int q = 0; q < 8; q++) {
            float2 f = unpackh2(w[q]);
            e[2 * q] = f.x; e[2 * q + 1] = f.y;
        }
    }
    int s = senders[i], r = receivers[i];
    float ns = g_nodes[s], nr = g_nodes[r];

    float h[HID];
#pragma unroll
    for (int j = 0; j < HID; j++) {
        float a = eb1[j];
#pragma unroll
        for (int k = 0; k < HID; k++) a = fmaf(ew1[j * 18 + k], e[k], a);
        a = fmaf(ew1[j * 18 + 16], ns, a);
        a = fmaf(ew1[j * 18 + 17], nr, a);
        h[j] = fmaxf(a, 0.f);
    }
    float e2[HID];
#pragma unroll
    for (int j = 0; j < HID; j++) {
        float a = eb2[j];
#pragma unroll
        for (int k = 0; k < HID; k++) a = fmaf(ew2[j * HID + k], h[k], a);
        e2[j] = a;
    }

    if (!LAST) {
        u32 u[8];
#pragma unroll
        for (int q = 0; q < 8; q++) u[q] = packh2(e2[2 * q], e2[2 * q + 1]);
        ep[0] = make_uint4(u[0], u[1], u[2], u[3]);
        ep[1] = make_uint4(u[4], u[5], u[6], u[7]);

        char* ps = (char*)g_agg_s + (size_t)s * 32;
        char* pr = (char*)g_agg_r + (size_t)r * 32;
        red_add_v4h(ps,      u[0], u[1], u[2], u[3]);
        red_add_v4h(ps + 16, u[4], u[5], u[6], u[7]);
        red_add_v4h(pr,      u[0], u[1], u[2], u[3]);
        red_add_v4h(pr + 16, u[4], u[5], u[6], u[7]);
    } else {
        float h2[HID];
#pragma unroll
        for (int j = 0; j < HID; j++) {
            float a = db1[j];
#pragma unroll
            for (int k = 0; k < HID; k++) a = fmaf(dw1[j * HID + k], e2[k], a);
            h2[j] = fmaxf(a, 0.f);
        }
        float sdec = db2s;
#pragma unroll
        for (int k = 0; k < HID; k++) sdec = fmaf(dw2[k], h2[k], sdec);
        out[i] = fmaf(alphas * g_norm, sdec, edges_init[i]);
    }
}

// ---------------- launch ----------------
extern "C" void kernel_launch(void* const* d_in, const int* in_sizes, int n_in,
                              void* d_out, int out_size)
{
    const float* nodes      = (const float*)d_in[0];
    const float* edges_init = (const float*)d_in[1];
    const int*   senders    = (const int*)d_in[2];
    const int*   receivers  = (const int*)d_in[3];
    const float* enc_w1 = (const float*)d_in[4];
    const float* enc_b1 = (const float*)d_in[5];
    const float* enc_w2 = (const float*)d_in[6];
    const float* enc_b2 = (const float*)d_in[7];
    const float* node_w1 = (const float*)d_in[8];
    const float* node_b1 = (const float*)d_in[9];
    const float* node_w2 = (const float*)d_in[10];
    const float* node_b2 = (const float*)d_in[11];
    const float* edge_w1 = (const float*)d_in[12];
    const float* edge_b1 = (const float*)d_in[13];
    const float* edge_w2 = (const float*)d_in[14];
    const float* edge_b2 = (const float*)d_in[15];
    const float* dec_w1 = (const float*)d_in[16];
    const float* dec_b1 = (const float*)d_in[17];
    const float* dec_w2 = (const float*)d_in[18];
    const float* dec_b2 = (const float*)d_in[19];
    const float* alpha  = (const float*)d_in[20];
    float* out = (float*)d_out;

    const int TB = 256;
    int zb = (NN * HID * 2 / 16 + TB - 1) / TB;
    k_zero<<<zb, TB>>>();                       // launch 0
    k_norm_part<<<1024, TB>>>(edges_init);      // launch 1
    k_norm_final<<<1, 1024>>>();                // launch 2

    int eb = (NE + TB - 1) / TB;
    int nb = (NN + TB - 1) / TB;

    k_enc<<<eb, TB>>>(edges_init, senders, receivers,
                      enc_w1, enc_b1, enc_w2, enc_b2);   // launch 3

    for (int r = 0; r < 3; r++) {
        if (r == 0)
            k_node<true><<<nb, TB>>>(nodes, node_w1, node_b1, node_w2, node_b2);   // launch 4
        else
            k_node<false><<<nb, TB>>>(nodes, node_w1, node_b1, node_w2, node_b2);

        if (r < 2)
            k_edge<false><<<eb, TB>>>(senders, receivers,                          // launch 5 (profiled)
                                      edge_w1, edge_b1, edge_w2, edge_b2,
                                      dec_w1, dec_b1, dec_w2, dec_b2,
                                      edges_init, alpha, out);
        else
            k_edge<true><<<eb, TB>>>(senders, receivers,
                                     edge_w1, edge_b1, edge_w2, edge_b2,
                                     dec_w1, dec_b1, dec_w2, dec_b2,
                                     edges_init, alpha, out);
    }
}